// round 6
// baseline (speedup 1.0000x reference)
#include <cuda_runtime.h>

#define B_    4096
#define NNODE 64
#define FIN   67
#define C1    64
#define C2    32
#define DFP   2048
#define H1D   400
#define H2D   64
#define NEDGE 512

typedef unsigned long long u64;

// ---------------- scratch (device globals; no allocations allowed) ----------------
__device__ float g_Ptd[NNODE * 132];             // P transposed + duplicated: [s][2d],(v,v)
__device__ float g_G1[B_ * NNODE * C1];          // gcn1 output (pre-BN)
__device__ float g_G2[B_ * NNODE * C2];          // gcn2 output (pre-BN)
__device__ float g_pool[B_ * C2];
__device__ float g_H1[B_ * H1D];
__device__ float g_H2[B_ * H2D];
__device__ float g_sum1[NNODE], g_ssq1[NNODE], g_sum2[NNODE], g_ssq2[NNODE];
__device__ float g_a1[NNODE], g_c1[NNODE], g_a2[NNODE], g_c2[NNODE];

// ---------------- packed f32x2 helpers ----------------
__device__ __forceinline__ void fma2(u64& d, u64 a, u64 b) {
    asm("fma.rn.f32x2 %0, %1, %2, %0;" : "+l"(d) : "l"(a), "l"(b));
}
__device__ __forceinline__ float2 unpk(u64 v) {
    float2 r; asm("mov.b64 {%0, %1}, %2;" : "=f"(r.x), "=f"(r.y) : "l"(v)); return r;
}

// ---------------- K0: build P (transposed, duplicated), zero stats ----------------
__global__ void k_prep(const int* __restrict__ el) {
    __shared__ float deg[NNODE];
    __shared__ float dinv[NNODE];
    __shared__ float Ps[NNODE * NNODE];
    int t = threadIdx.x;
    if (t < NNODE) deg[t] = 0.f;
    for (int i = t; i < NNODE * NNODE; i += 256) Ps[i] = 0.f;
    __syncthreads();
    for (int i = t; i < NEDGE + NNODE; i += 256) {
        int d = (i < NEDGE) ? el[NEDGE + i] : (i - NEDGE);
        atomicAdd(&deg[d], 1.f);
    }
    __syncthreads();
    if (t < NNODE) dinv[t] = (deg[t] > 0.f) ? rsqrtf(deg[t]) : 0.f;
    __syncthreads();
    for (int i = t; i < NEDGE + NNODE; i += 256) {
        int s = (i < NEDGE) ? el[i] : (i - NEDGE);
        int d = (i < NEDGE) ? el[NEDGE + i] : (i - NEDGE);
        atomicAdd(&Ps[d * NNODE + s], dinv[s] * dinv[d]);
    }
    __syncthreads();
    for (int i = t; i < NNODE * NNODE; i += 256) {
        int d = i >> 6, s = i & 63;
        float v = Ps[i];
        g_Ptd[s * 132 + 2 * d]     = v;
        g_Ptd[s * 132 + 2 * d + 1] = v;
    }
    if (t < NNODE) { g_sum1[t] = 0.f; g_ssq1[t] = 0.f; g_sum2[t] = 0.f; g_ssq2[t] = 0.f; }
}

// ---------------- fused GCN1: G1[b] = P @ (X[b] @ W1^T) + b1, plus BN1 stats --------
// dyn smem: U[8844] (X dup then Ptd) | Ws[67*68] | Ys[64*68]  = 17752 floats
__global__ void k_fused1(const float* __restrict__ xn, const float* __restrict__ W1,
                         const float* __restrict__ b1) {
    extern __shared__ float sm[];
    float* U  = sm;                   // phase1: Xdup[k][2m] (67x132); phase2: Ptd (64x132)
    float* Ws = sm + 8844;            // [k][n], 67x68
    float* Ys = sm + 8844 + 4556;     // [m][n], 64x68

    int b = blockIdx.x, t = threadIdx.x;
    const float* Xb = xn + (size_t)b * (NNODE * FIN);
    for (int i = t; i < NNODE * FIN; i += 256) {
        int r = i / FIN, k = i - r * FIN;
        float v = Xb[i];
        U[k * 132 + 2 * r] = v; U[k * 132 + 2 * r + 1] = v;
    }
    for (int i = t; i < C1 * FIN; i += 256) {
        int n = i / FIN, k = i - n * FIN;
        Ws[k * 68 + n] = W1[i];
    }
    __syncthreads();

    int tm = (t >> 4) * 4, tn = (t & 15) * 4;

    // phase 1: Y = X @ W1^T
    u64 acc[4][2] = {};
    #pragma unroll 4
    for (int k = 0; k < FIN; k++) {
        ulonglong2 a01 = *reinterpret_cast<const ulonglong2*>(&U[k * 132 + 2 * tm]);
        ulonglong2 a23 = *reinterpret_cast<const ulonglong2*>(&U[k * 132 + 2 * tm + 4]);
        ulonglong2 bb  = *reinterpret_cast<const ulonglong2*>(&Ws[k * 68 + tn]);
        fma2(acc[0][0], a01.x, bb.x); fma2(acc[0][1], a01.x, bb.y);
        fma2(acc[1][0], a01.y, bb.x); fma2(acc[1][1], a01.y, bb.y);
        fma2(acc[2][0], a23.x, bb.x); fma2(acc[2][1], a23.x, bb.y);
        fma2(acc[3][0], a23.y, bb.x); fma2(acc[3][1], a23.y, bb.y);
    }
    #pragma unroll
    for (int i = 0; i < 4; i++) {
        ulonglong2 v; v.x = acc[i][0]; v.y = acc[i][1];   // packed = 2 consecutive floats
        *reinterpret_cast<ulonglong2*>(&Ys[(tm + i) * 68 + tn]) = v;
    }
    __syncthreads();
    for (int i = t; i < NNODE * 132; i += 256) U[i] = g_Ptd[i];
    __syncthreads();

    // phase 2: G1 = P @ Y  (rows = dst node d, cols = out channel o)
    u64 g[4][2] = {};
    #pragma unroll 4
    for (int s = 0; s < NNODE; s++) {
        ulonglong2 a01 = *reinterpret_cast<const ulonglong2*>(&U[s * 132 + 2 * tm]);
        ulonglong2 a23 = *reinterpret_cast<const ulonglong2*>(&U[s * 132 + 2 * tm + 4]);
        ulonglong2 bb  = *reinterpret_cast<const ulonglong2*>(&Ys[s * 68 + tn]);
        fma2(g[0][0], a01.x, bb.x); fma2(g[0][1], a01.x, bb.y);
        fma2(g[1][0], a01.y, bb.x); fma2(g[1][1], a01.y, bb.y);
        fma2(g[2][0], a23.x, bb.x); fma2(g[2][1], a23.x, bb.y);
        fma2(g[3][0], a23.y, bb.x); fma2(g[3][1], a23.y, bb.y);
    }

    float4 bv = *reinterpret_cast<const float4*>(&b1[tn]);
    float sums[4], ssqs[4];
    float* outp = g_G1 + (size_t)b * (NNODE * C1);
    #pragma unroll
    for (int i = 0; i < 4; i++) {
        float2 p0 = unpk(g[i][0]), p1 = unpk(g[i][1]);
        float v0 = p0.x + bv.x, v1 = p0.y + bv.y, v2 = p1.x + bv.z, v3 = p1.y + bv.w;
        *reinterpret_cast<float4*>(&outp[(tm + i) * 64 + tn]) = make_float4(v0, v1, v2, v3);
        sums[i] = (v0 + v1) + (v2 + v3);
        ssqs[i] = fmaf(v0, v0, fmaf(v1, v1, fmaf(v2, v2, v3 * v3)));
    }
    #pragma unroll
    for (int off = 8; off >= 1; off >>= 1) {
        #pragma unroll
        for (int i = 0; i < 4; i++) {
            sums[i] += __shfl_xor_sync(0xffffffffu, sums[i], off);
            ssqs[i] += __shfl_xor_sync(0xffffffffu, ssqs[i], off);
        }
    }
    if ((t & 15) == 0) {
        #pragma unroll
        for (int i = 0; i < 4; i++) {
            atomicAdd(&g_sum1[tm + i], sums[i]);
            atomicAdd(&g_ssq1[tm + i], ssqs[i]);
        }
    }
}

// ---------------- finalize BN scale/shift ----------------
__global__ void k_bnfin(int stage, const float* __restrict__ gamma,
                        const float* __restrict__ beta, float invn) {
    int t = threadIdx.x;
    if (t < NNODE) {
        const float* sum = stage ? g_sum2 : g_sum1;
        const float* ssq = stage ? g_ssq2 : g_ssq1;
        float* a = stage ? g_a2 : g_a1;
        float* c = stage ? g_c2 : g_c1;
        float m = sum[t] * invn;
        float v = ssq[t] * invn - m * m;
        float r = rsqrtf(v + 1e-5f);
        float aa = gamma[t] * r;
        a[t] = aa;
        c[t] = beta[t] - m * aa;
    }
}

// ---------------- fused GCN2: G2[b] = P @ (relu(bn1(G1[b])) @ W2^T) + b2, + stats2 ---
// dyn smem: U[8448] (A dup then Ptd) | W2t[64*36] | Zs[64*36] | a1s[64] | c1s[64]
__global__ void k_fused2(const float* __restrict__ W2, const float* __restrict__ b2) {
    extern __shared__ float sm[];
    float* U   = sm;                       // 64x132
    float* W2t = sm + 8448;                // [c][j], 64x36
    float* Zs  = sm + 8448 + 2304;         // [s][j], 64x36
    float* a1s = sm + 8448 + 4608;
    float* c1s = a1s + 64;

    int b = blockIdx.x, t = threadIdx.x;
    if (t < 64) { a1s[t] = g_a1[t]; c1s[t] = g_c1[t]; }
    __syncthreads();

    const float* Gb = g_G1 + (size_t)b * (NNODE * C1);
    for (int i = t; i < NNODE * C1; i += 256) {
        int d = i >> 6, c = i & 63;
        float v = fmaxf(fmaf(Gb[i], a1s[d], c1s[d]), 0.f);
        U[c * 132 + 2 * d] = v; U[c * 132 + 2 * d + 1] = v;
    }
    for (int i = t; i < C2 * C1; i += 256) {
        int j = i >> 6, c = i & 63;
        W2t[c * 36 + j] = W2[i];
    }
    __syncthreads();

    int tm = (t >> 4) * 4;           // 4 rows (nodes)
    int j0 = (t & 15) * 2;           // 2 cols (channels)

    // phase 1: Z = relu(bn(G1)) @ W2^T
    u64 z[4] = {};
    #pragma unroll 4
    for (int c = 0; c < C1; c++) {
        ulonglong2 a01 = *reinterpret_cast<const ulonglong2*>(&U[c * 132 + 2 * tm]);
        ulonglong2 a23 = *reinterpret_cast<const ulonglong2*>(&U[c * 132 + 2 * tm + 4]);
        u64 w = *reinterpret_cast<const u64*>(&W2t[c * 36 + j0]);
        fma2(z[0], a01.x, w); fma2(z[1], a01.y, w);
        fma2(z[2], a23.x, w); fma2(z[3], a23.y, w);
    }
    #pragma unroll
    for (int i = 0; i < 4; i++)
        *reinterpret_cast<u64*>(&Zs[(tm + i) * 36 + j0]) = z[i];
    __syncthreads();
    for (int i = t; i < NNODE * 132; i += 256) U[i] = g_Ptd[i];
    __syncthreads();

    // phase 2: G2 = P @ Z
    u64 g[4] = {};
    #pragma unroll 4
    for (int s = 0; s < NNODE; s++) {
        ulonglong2 a01 = *reinterpret_cast<const ulonglong2*>(&U[s * 132 + 2 * tm]);
        ulonglong2 a23 = *reinterpret_cast<const ulonglong2*>(&U[s * 132 + 2 * tm + 4]);
        u64 zz = *reinterpret_cast<const u64*>(&Zs[s * 36 + j0]);
        fma2(g[0], a01.x, zz); fma2(g[1], a01.y, zz);
        fma2(g[2], a23.x, zz); fma2(g[3], a23.y, zz);
    }

    float2 bv = *reinterpret_cast<const float2*>(&b2[j0]);
    float sums[4], ssqs[4];
    float* outp = g_G2 + (size_t)b * (NNODE * C2);
    #pragma unroll
    for (int i = 0; i < 4; i++) {
        float2 p = unpk(g[i]);
        float v0 = p.x + bv.x, v1 = p.y + bv.y;
        *reinterpret_cast<float2*>(&outp[(tm + i) * 32 + j0]) = make_float2(v0, v1);
        sums[i] = v0 + v1;
        ssqs[i] = fmaf(v0, v0, v1 * v1);
    }
    #pragma unroll
    for (int off = 8; off >= 1; off >>= 1) {
        #pragma unroll
        for (int i = 0; i < 4; i++) {
            sums[i] += __shfl_xor_sync(0xffffffffu, sums[i], off);
            ssqs[i] += __shfl_xor_sync(0xffffffffu, ssqs[i], off);
        }
    }
    if ((t & 15) == 0) {
        #pragma unroll
        for (int i = 0; i < 4; i++) {
            atomicAdd(&g_sum2[tm + i], sums[i]);
            atomicAdd(&g_ssq2[tm + i], ssqs[i]);
        }
    }
}

// ---------------- bn2 + relu + max-pool over nodes ----------------
__global__ void k_pool() {
    __shared__ float a2s[64], c2s[64];
    int t = threadIdx.x;
    if (t < 64) { a2s[t] = g_a2[t]; c2s[t] = g_c2[t]; }
    __syncthreads();
    int bl = t >> 5, j = t & 31;
    int b = blockIdx.x * 8 + bl;
    const float* src = g_G2 + (size_t)b * 2048 + j;
    float m = 0.f;   // relu outputs >= 0
    #pragma unroll 8
    for (int d = 0; d < 64; d++) {
        float v = fmaxf(fmaf(src[d * 32], a2s[d], c2s[d]), 0.f);
        m = fmaxf(m, v);
    }
    g_pool[b * 32 + j] = m;
}

// ---------------- MLP GEMM (f32x2): C = relu(A @ B^T + bias) ----------------
template <int MODE, bool GN>
__global__ void k_mlp(const float* __restrict__ Ain, const float* __restrict__ Bw,
                      const float* __restrict__ bias, int Ncols, int K) {
    __shared__ __align__(16) float As2[16 * 132];   // [kk][2m] duplicated
    __shared__ __align__(16) float Bs[16 * 68];     // [kk][n]
    const float* A = (MODE == 0) ? Ain : g_H1;
    float* C = (MODE == 0) ? g_H1 : g_H2;
    int m0 = blockIdx.x * 64, n0 = blockIdx.y * 64;
    int t = threadIdx.x;
    int tm = (t >> 4) * 4, tn = (t & 15) * 4;
    u64 acc[4][2] = {};
    for (int k0 = 0; k0 < K; k0 += 16) {
        for (int i = t; i < 1024; i += 256) {
            int r = i >> 4, kk = i & 15;
            float av = A[(size_t)(m0 + r) * K + k0 + kk];
            As2[kk * 132 + 2 * r] = av; As2[kk * 132 + 2 * r + 1] = av;
            float bv = 0.f;
            if (!GN || (n0 + r) < Ncols) bv = Bw[(size_t)(n0 + r) * K + k0 + kk];
            Bs[kk * 68 + r] = bv;
        }
        __syncthreads();
        #pragma unroll
        for (int kk = 0; kk < 16; kk++) {
            ulonglong2 a01 = *reinterpret_cast<const ulonglong2*>(&As2[kk * 132 + 2 * tm]);
            ulonglong2 a23 = *reinterpret_cast<const ulonglong2*>(&As2[kk * 132 + 2 * tm + 4]);
            ulonglong2 bb  = *reinterpret_cast<const ulonglong2*>(&Bs[kk * 68 + tn]);
            fma2(acc[0][0], a01.x, bb.x); fma2(acc[0][1], a01.x, bb.y);
            fma2(acc[1][0], a01.y, bb.x); fma2(acc[1][1], a01.y, bb.y);
            fma2(acc[2][0], a23.x, bb.x); fma2(acc[2][1], a23.x, bb.y);
            fma2(acc[3][0], a23.y, bb.x); fma2(acc[3][1], a23.y, bb.y);
        }
        __syncthreads();
    }
    #pragma unroll
    for (int i = 0; i < 4; i++) {
        int row = m0 + tm + i;
        float2 p0 = unpk(acc[i][0]), p1 = unpk(acc[i][1]);
        float v[4] = { p0.x, p0.y, p1.x, p1.y };
        #pragma unroll
        for (int j = 0; j < 4; j++) {
            int col = n0 + tn + j;
            if (!GN || col < Ncols) {
                C[(size_t)row * Ncols + col] = fmaxf(v[j] + __ldg(&bias[col]), 0.f);
            }
        }
    }
}

// ---------------- final: out = [pool, H2] @ Wfc^T + bfc ----------------
__global__ void k_final(const float* __restrict__ Wfc, const float* __restrict__ bfc,
                        float* __restrict__ out) {
    __shared__ float Ws[192];
    int t = threadIdx.x;
    if (t < 192) Ws[t] = Wfc[t];
    __syncthreads();
    int b = blockIdx.x * 256 + t;
    float a0 = __ldg(&bfc[0]), a1 = __ldg(&bfc[1]);
    const float* pp = g_pool + b * 32;
    const float* hh = g_H2 + b * 64;
    #pragma unroll
    for (int j = 0; j < 32; j++) {
        float v = pp[j];
        a0 = fmaf(v, Ws[j], a0);
        a1 = fmaf(v, Ws[96 + j], a1);
    }
    #pragma unroll
    for (int j = 0; j < 64; j++) {
        float v = hh[j];
        a0 = fmaf(v, Ws[32 + j], a0);
        a1 = fmaf(v, Ws[128 + j], a1);
    }
    out[b * 2]     = a0;
    out[b * 2 + 1] = a1;
}

// ---------------- launch ----------------
extern "C" void kernel_launch(void* const* d_in, const int* in_sizes, int n_in,
                              void* d_out, int out_size) {
    const float* xf  = (const float*)d_in[0];
    const float* xn  = (const float*)d_in[1];
    const int*   el  = (const int*)  d_in[2];
    const float* W1  = (const float*)d_in[3];
    const float* b1  = (const float*)d_in[4];
    const float* g1  = (const float*)d_in[5];
    const float* be1 = (const float*)d_in[6];
    const float* W2  = (const float*)d_in[7];
    const float* b2  = (const float*)d_in[8];
    const float* g2  = (const float*)d_in[9];
    const float* be2 = (const float*)d_in[10];
    const float* Wl1 = (const float*)d_in[11];
    const float* bl1 = (const float*)d_in[12];
    const float* Wl2 = (const float*)d_in[13];
    const float* bl2 = (const float*)d_in[14];
    const float* Wfc = (const float*)d_in[15];
    const float* bfc = (const float*)d_in[16];
    float* out = (float*)d_out;

    const int SMEM1 = 17752 * 4;   // 71008 B
    const int SMEM2 = 13184 * 4;   // 52736 B
    cudaFuncSetAttribute(k_fused1, cudaFuncAttributeMaxDynamicSharedMemorySize, SMEM1);
    cudaFuncSetAttribute(k_fused2, cudaFuncAttributeMaxDynamicSharedMemorySize, SMEM2);

    k_prep<<<1, 256>>>(el);

    // graph path (fused GEMMs with in-kernel BN stats)
    k_fused1<<<B_, 256, SMEM1>>>(xn, W1, b1);
    k_bnfin<<<1, 64>>>(0, g1, be1, 1.0f / (float)(B_ * C1));
    k_fused2<<<B_, 256, SMEM2>>>(W2, b2);
    k_bnfin<<<1, 64>>>(1, g2, be2, 1.0f / (float)(B_ * C2));
    k_pool<<<B_ / 8, 256>>>();

    // fingerprint MLP path
    k_mlp<0, true ><<<dim3(B_ / 64, 7), 256>>>(xf, Wl1, bl1, H1D, DFP);
    k_mlp<1, false><<<dim3(B_ / 64, 1), 256>>>(nullptr, Wl2, bl2, H2D, H1D);

    k_final<<<B_ / 256, 256>>>(Wfc, bfc, out);
}